// round 16
// baseline (speedup 1.0000x reference)
#include <cuda_runtime.h>
#include <cuda_bf16.h>
#include <math.h>

// ---------------- problem constants ----------------
#define MAX_NODES 200000
#define MAX_EDGES 3200000
#define SCAN_B    1024
#define MAX_ST    256          // scan state slots (196 blocks + counter)

// ---------------- device scratch (no allocations allowed) --------------
__device__ int                g_deg[MAX_NODES];
__device__ int                g_rowptr[MAX_NODES + 1];
__device__ int                g_fill[MAX_NODES];
__device__ unsigned long long g_state[MAX_ST];   // decoupled-lookback state (+counter in [255])
__device__ int                g_csr[MAX_EDGES];
__device__ float              g_mean[MAX_NODES * 32];

// ---------------- f32x2 packed helpers ----------------
__device__ __forceinline__ unsigned long long pk2(float a, float b) {
    unsigned long long r;
    asm("mov.b64 %0, {%1, %2};" : "=l"(r) : "f"(a), "f"(b));
    return r;
}
__device__ __forceinline__ void upk2(unsigned long long v, float& a, float& b) {
    asm("mov.b64 {%0, %1}, %2;" : "=f"(a), "=f"(b) : "l"(v));
}
__device__ __forceinline__ unsigned long long fmax2(unsigned long long a, unsigned long long b,
                                                    unsigned long long c) {
    unsigned long long r;
    asm("fma.rn.f32x2 %0, %1, %2, %3;" : "=l"(r) : "l"(a), "l"(b), "l"(c));
    return r;
}

// ---------------- CSR construction ----------------
__global__ void k_hist(const int* __restrict__ dst, int* deg, int E) {
    int e = blockIdx.x * blockDim.x + threadIdx.x;
    if (e < E) atomicAdd(&deg[dst[e]], 1);
}

// Single-pass decoupled-lookback exclusive scan of deg -> rowptr (+fill copy).
// state[bid] packs (flag<<32 | value); flag: 0=invalid, 1=aggregate, 2=prefix.
// All 196 blocks are co-resident on 148 SMs -> lookback cannot deadlock.
__global__ void __launch_bounds__(SCAN_B)
k_scan_dl(const int* __restrict__ deg, int* rowptr, int* fill,
          unsigned long long* state, int n, int E)
{
    __shared__ int sh[SCAN_B];
    __shared__ int s_bid;
    __shared__ int s_prefix;

    const int tid = threadIdx.x;
    if (tid == 0)
        s_bid = (int)atomicAdd(&state[MAX_ST - 1], 1ull);
    __syncthreads();
    const int bid = s_bid;

    const int i = bid * SCAN_B + tid;
    const int d = (i < n) ? deg[i] : 0;
    sh[tid] = d;
    __syncthreads();
    int val = d;
    #pragma unroll
    for (int off = 1; off < SCAN_B; off <<= 1) {
        int t = (tid >= off) ? sh[tid - off] : 0;
        __syncthreads();
        val += t;
        sh[tid] = val;
        __syncthreads();
    }
    const int total = sh[SCAN_B - 1];

    if (tid == 0) {
        if (bid == 0) {
            atomicExch(&state[0], (2ull << 32) | (unsigned int)total);
            s_prefix = 0;
        } else {
            atomicExch(&state[bid], (1ull << 32) | (unsigned int)total);
            int pref = 0;
            int j = bid - 1;
            while (j >= 0) {
                unsigned long long st;
                do { st = atomicAdd(&state[j], 0ull); } while ((st >> 32) == 0ull);
                pref += (int)(unsigned int)st;
                if ((st >> 32) == 2ull) break;
                j--;
            }
            atomicExch(&state[bid], (2ull << 32) | (unsigned int)(pref + total));
            s_prefix = pref;
        }
    }
    __syncthreads();
    const int pref = s_prefix;

    if (i < n) {
        const int r = pref + val - d;   // exclusive prefix
        rowptr[i] = r;
        fill[i]   = r;
        if (i == n - 1) rowptr[n] = E;
    }
}

__global__ void k_fill(const int* __restrict__ src, const int* __restrict__ dst,
                       int* fill, int* csr, int E) {
    int e = blockIdx.x * blockDim.x + threadIdx.x;
    if (e < E) {
        int pos = atomicAdd(&fill[dst[e]], 1);
        csr[pos] = src[e];
    }
}

// ---------------- gather: warp-per-node neighbor mean ----------------
// Lean (~40 regs, no smem) -> high occupancy. Single fully-predicated 8-wide
// loop: 8 independent feature loads in flight per warp, no tail code.
__global__ void __launch_bounds__(256)
k_gather(const float* __restrict__ h_in, int stride,
         const int* __restrict__ rowptr, const int* __restrict__ csr,
         float* __restrict__ meanb, int n)
{
    const int lane = threadIdx.x & 31;
    const int v = (blockIdx.x * blockDim.x + threadIdx.x) >> 5;
    if (v >= n) return;

    const int rs = __ldg(&rowptr[v]);
    const int re = __ldg(&rowptr[v + 1]);
    const int deg = re - rs;

    float a[8];
    #pragma unroll
    for (int i = 0; i < 8; i++) a[i] = 0.f;

    #pragma unroll 1
    for (int e = rs; e < re; e += 8) {
        int s[8];
        #pragma unroll
        for (int i = 0; i < 8; i++)
            s[i] = ((e + i) < re) ? __ldg(&csr[e + i]) : 0;
        float f[8];
        #pragma unroll
        for (int i = 0; i < 8; i++)
            f[i] = ((e + i) < re) ? __ldg(&h_in[s[i] * stride + lane]) : 0.f;
        #pragma unroll
        for (int i = 0; i < 8; i++) a[i] += f[i];
    }

    const float acc = ((a[0] + a[1]) + (a[2] + a[3])) + ((a[4] + a[5]) + (a[6] + a[7]));
    const float inv = (deg > 0) ? (1.0f / (float)deg) : 0.0f;
    meanb[v * 32 + lane] = acc * inv;
}

// ---------------- dense: thread-per-node GEMV (packed f32x2) ----------------
__global__ void __launch_bounds__(256)
k_dense(const float* __restrict__ h_in, int stride,
        const float* __restrict__ meanb,
        const float* __restrict__ Ws, const float* __restrict__ Wn,
        const float* __restrict__ bias,
        float* __restrict__ cs_out, int n)
{
    __shared__ __align__(16) float sW[2048];   // [64 k][32 j]: Ws rows then Wn
    __shared__ float sB[32];

    const int tid = threadIdx.x;
    for (int i = tid; i < 1024; i += 256) {
        sW[i]        = Ws[i];
        sW[1024 + i] = Wn[i];
    }
    if (tid < 32) sB[tid] = bias[tid];
    __syncthreads();

    const int v = blockIdx.x * blockDim.x + tid;
    if (v >= n) return;

    const ulonglong2* sWu = reinterpret_cast<const ulonglong2*>(sW);

    unsigned long long acc2[16];
    #pragma unroll
    for (int j = 0; j < 16; j++) acc2[j] = pk2(sB[2 * j], sB[2 * j + 1]);

    float vs[32];
    {
        const float4* selfp = reinterpret_cast<const float4*>(h_in + v * stride);
        #pragma unroll
        for (int q = 0; q < 8; q++) {
            float4 t = __ldg(&selfp[q]);
            vs[4 * q + 0] = t.x; vs[4 * q + 1] = t.y;
            vs[4 * q + 2] = t.z; vs[4 * q + 3] = t.w;
        }
    }
    #pragma unroll
    for (int k = 0; k < 32; k++) {
        const unsigned long long vv = pk2(vs[k], vs[k]);
        #pragma unroll
        for (int q = 0; q < 8; q++) {
            ulonglong2 w = sWu[k * 8 + q];
            acc2[2 * q + 0] = fmax2(w.x, vv, acc2[2 * q + 0]);
            acc2[2 * q + 1] = fmax2(w.y, vv, acc2[2 * q + 1]);
        }
    }

    float vm[32];
    {
        const float4* mrow = reinterpret_cast<const float4*>(meanb + v * 32);
        #pragma unroll
        for (int q = 0; q < 8; q++) {
            float4 t = __ldg(&mrow[q]);
            vm[4 * q + 0] = t.x; vm[4 * q + 1] = t.y;
            vm[4 * q + 2] = t.z; vm[4 * q + 3] = t.w;
        }
    }
    #pragma unroll
    for (int k = 0; k < 32; k++) {
        const unsigned long long vv = pk2(vm[k], vm[k]);
        #pragma unroll
        for (int q = 0; q < 8; q++) {
            ulonglong2 w = sWu[(32 + k) * 8 + q];
            acc2[2 * q + 0] = fmax2(w.x, vv, acc2[2 * q + 0]);
            acc2[2 * q + 1] = fmax2(w.y, vv, acc2[2 * q + 1]);
        }
    }

    float4* outp = reinterpret_cast<float4*>(cs_out + v * 128);
    #pragma unroll
    for (int q = 0; q < 8; q++) {
        float x0, x1, x2, x3;
        upk2(acc2[2 * q + 0], x0, x1);
        upk2(acc2[2 * q + 1], x2, x3);
        float4 o;
        o.x = tanhf(x0); o.y = tanhf(x1);
        o.z = tanhf(x2); o.w = tanhf(x3);
        outp[q] = o;
    }
}

// ---------------- pair MLP: 8 pairs per block, W1 in shared --------------------
#define PPB 8
__global__ void __launch_bounds__(128)
k_pair(const float* __restrict__ cs, const int* __restrict__ uidx,
       const int* __restrict__ iidx,
       const float* __restrict__ W1, const float* __restrict__ bl1,
       const float* __restrict__ W2, const float* __restrict__ bl2,
       float* __restrict__ score, int n_pairs)
{
    extern __shared__ float sh[];
    float* sW1 = sh;                 // 256*128
    float* sPT = sW1 + 256 * 128;    // [256][PPB]
    float* sH  = sPT + 256 * PPB;    // [PPB][128]

    const int tid  = threadIdx.x;
    const int warp = tid >> 5;
    const int lane = tid & 31;

    for (int i = tid; i < 256 * 128; i += 128) sW1[i] = W1[i];
    const float b1 = bl1[tid];
    const float w2 = W2[tid];
    const float b2 = bl2[0];

    const int pbase = blockIdx.x * PPB;
    #pragma unroll
    for (int p = 0; p < PPB; p++) {
        int pr = pbase + p;
        int safe = (pr < n_pairs) ? pr : 0;
        int u  = uidx[safe];
        int it = iidx[safe];
        sPT[tid * PPB + p]         = cs[u  * 128 + tid];
        sPT[(128 + tid) * PPB + p] = cs[it * 128 + tid];
    }
    __syncthreads();

    float acc[PPB];
    #pragma unroll
    for (int p = 0; p < PPB; p++) acc[p] = b1;

    #pragma unroll 4
    for (int k = 0; k < 256; k++) {
        float w = sW1[k * 128 + tid];
        float4 pa = *reinterpret_cast<const float4*>(&sPT[k * PPB]);
        float4 pb = *reinterpret_cast<const float4*>(&sPT[k * PPB + 4]);
        acc[0] = fmaf(pa.x, w, acc[0]);
        acc[1] = fmaf(pa.y, w, acc[1]);
        acc[2] = fmaf(pa.z, w, acc[2]);
        acc[3] = fmaf(pa.w, w, acc[3]);
        acc[4] = fmaf(pb.x, w, acc[4]);
        acc[5] = fmaf(pb.y, w, acc[5]);
        acc[6] = fmaf(pb.z, w, acc[6]);
        acc[7] = fmaf(pb.w, w, acc[7]);
    }

    #pragma unroll
    for (int p = 0; p < PPB; p++)
        sH[p * 128 + tid] = fmaxf(acc[p], 0.0f) * w2;
    __syncthreads();

    for (int p = warp; p < PPB; p += 4) {
        float v = sH[p * 128 + lane] + sH[p * 128 + 32 + lane]
                + sH[p * 128 + 64 + lane] + sH[p * 128 + 96 + lane];
        #pragma unroll
        for (int o = 16; o > 0; o >>= 1) v += __shfl_down_sync(0xffffffffu, v, o);
        if (lane == 0 && (pbase + p) < n_pairs)
            score[pbase + p] = 1.0f / (1.0f + expf(-(v + b2)));
    }
}

// ---------------- launch ----------------
extern "C" void kernel_launch(void* const* d_in, const int* in_sizes, int n_in,
                              void* d_out, int out_size)
{
    const float* x        = (const float*)d_in[0];
    const int*   src      = (const int*)  d_in[1];
    const int*   dst      = (const int*)  d_in[2];
    const int*   user_idx = (const int*)  d_in[3];
    const int*   item_idx = (const int*)  d_in[4];
    const float* Wsx[4] = { (const float*)d_in[5],  (const float*)d_in[8],
                            (const float*)d_in[11], (const float*)d_in[14] };
    const float* Wnx[4] = { (const float*)d_in[6],  (const float*)d_in[9],
                            (const float*)d_in[12], (const float*)d_in[15] };
    const float* bx[4]  = { (const float*)d_in[7],  (const float*)d_in[10],
                            (const float*)d_in[13], (const float*)d_in[16] };
    const float* W1  = (const float*)d_in[17];
    const float* bl1 = (const float*)d_in[18];
    const float* W2  = (const float*)d_in[19];
    const float* bl2 = (const float*)d_in[20];

    const int N = in_sizes[0] / 32;
    const int E = in_sizes[1];
    const int P = in_sizes[3];

    float* out   = (float*)d_out;
    float* score = out;                 // [P]
    float* cs    = out + P;             // [N,128] concat_states

    void *p_deg, *p_rowptr, *p_fill, *p_state, *p_csr, *p_mean;
    cudaGetSymbolAddress(&p_deg,    g_deg);
    cudaGetSymbolAddress(&p_rowptr, g_rowptr);
    cudaGetSymbolAddress(&p_fill,   g_fill);
    cudaGetSymbolAddress(&p_state,  g_state);
    cudaGetSymbolAddress(&p_csr,    g_csr);
    cudaGetSymbolAddress(&p_mean,   g_mean);
    int*   deg    = (int*)p_deg;
    int*   rowptr = (int*)p_rowptr;
    int*   fill   = (int*)p_fill;
    unsigned long long* state = (unsigned long long*)p_state;
    int*   csr    = (int*)p_csr;
    float* meanb  = (float*)p_mean;

    // --- CSR build (memsets instead of zeroing kernels) ---
    cudaMemsetAsync(deg,   0, (size_t)N * sizeof(int));
    cudaMemsetAsync(state, 0, (size_t)MAX_ST * sizeof(unsigned long long));
    k_hist<<<(E + 255) / 256, 256>>>(dst, deg, E);
    const int nb = (N + SCAN_B - 1) / SCAN_B;
    k_scan_dl<<<nb, SCAN_B>>>(deg, rowptr, fill, state, N, E);
    k_fill<<<(E + 255) / 256, 256>>>(src, dst, fill, csr, E);

    // --- 4 SAGE layers: gather (warp/node) + dense (thread/node) ---
    const int ggrid = (N * 32 + 255) / 256;   // 8 warps/block, 1 node/warp
    const int dgrid = (N + 255) / 256;
    for (int l = 0; l < 4; l++) {
        const float* hin   = (l == 0) ? x  : cs + 32 * (l - 1);
        const int    strid = (l == 0) ? 32 : 128;
        k_gather<<<ggrid, 256>>>(hin, strid, rowptr, csr, meanb, N);
        k_dense <<<dgrid, 256>>>(hin, strid, meanb, Wsx[l], Wnx[l], bx[l],
                                 cs + 32 * l, N);
    }

    // --- pair MLP ---
    const int smem = (256 * 128 + 256 * PPB + PPB * 128) * (int)sizeof(float);
    cudaFuncSetAttribute(k_pair, cudaFuncAttributeMaxDynamicSharedMemorySize, smem);
    k_pair<<<(P + PPB - 1) / PPB, 128, smem>>>(cs, user_idx, item_idx,
                                               W1, bl1, W2, bl2, score, P);
}